// round 4
// baseline (speedup 1.0000x reference)
#include <cuda_runtime.h>
#include <cuda_fp16.h>
#include <math.h>

#define NPOS 392
#define KK   288          // K*K*IN_CAPS
#define OC   32
#define PS   16
#define OSZ  512          // OC*PS
#define CEPS 1e-8f
#define LN2PI 1.8378770664093453f
#define NTHREADS 512
#define KH    144         // KK/2

// vote scratch (fp16): 392 * 288 * 512 * 2B = 115.6 MB
__device__ __half g_votes[(size_t)NPOS * KK * OSZ];

extern __shared__ float smem[];

__global__ __launch_bounds__(NTHREADS, 2)
void convcaps_kernel(const float* __restrict__ x,
                     const float* __restrict__ wts,
                     const float* __restrict__ beta_u,
                     const float* __restrict__ beta_a,
                     float* __restrict__ out)
{
    const int n    = blockIdx.x;
    const int tid  = threadIdx.x;

    // ---- smem carve (~28.5 KB) ----
    float* sP    = smem;            // 4608  poses [k][s] (reused as sPart after vote gen)
    float* sCk   = sP + KK*PS;      // 288   ck = a/(a+eps)
    float* sM    = sCk + KK;        // 512   M accumulators [o*16+s]
    float* sQ    = sM + 512;        // 512   Q accumulators
    float* sMean = sQ + 512;        // 544   mean [o*17+s]
    float* sIv   = sMean + 544;     // 544   1/(2 std^2)
    float* sRsA  = sIv + 544;       // 32    rsum (iter 1)
    float* sRsB  = sRsA + 32;       // 32    rsum (iter 2)
    float* sAct  = sRsB + 32;       // 32
    float* sC    = sAct + 32;       // 32
    float* sCkS  = sC + 32;         // 1
    float* sPart = sP;              // 1024  (alias: valid after vote gen)

    if (tid == 0) *sCkS = 0.f;
    __syncthreads();

    // ---- Phase 0: gather input tile (reference reshape semantics) ----
    const int b = n / 49;
    const int m = n - b*49;
    for (int idx = tid; idx < 9*544; idx += NTHREADS) {
        int j   = idx / 544;
        int c   = idx - j*544;
        int t9  = 9*m + j;
        int khw = t9 / 49;
        int oyx = t9 - khw*49;
        int oy  = oyx / 7;
        int ox  = oyx - oy*7;
        int kh  = khw / 3;
        int kw  = khw - kh*3;
        int h   = 2*oy + kh;
        int w   = 2*ox + kw;
        float v = x[(size_t)(((b*16 + h)*16) + w)*544 + c];
        if (c < 512) {
            sP[j*512 + c] = v;
        } else {
            float ck = v / (v + CEPS);
            sCk[j*32 + (c - 512)] = ck;
            atomicAdd(sCkS, ck);
        }
    }
    __syncthreads();

    // ---- Phase 1: votes v[k,o,:] = p[k,:] (4x4) @ W[k,o] (4x4), fp16 store ----
    __half* vbase = g_votes + (size_t)n * (KK*OSZ);
    for (int pair = tid; pair < KK*OC; pair += NTHREADS) {
        int k = pair >> 5;
        const float* p = sP + k*PS;
        const float4* wv4 = (const float4*)(wts + (size_t)pair*16);
        float w0[16];
        #pragma unroll
        for (int qi = 0; qi < 4; ++qi) {
            float4 t = wv4[qi];
            w0[4*qi+0]=t.x; w0[4*qi+1]=t.y; w0[4*qi+2]=t.z; w0[4*qi+3]=t.w;
        }
        __half2 hh[8];
        #pragma unroll
        for (int i = 0; i < 4; ++i) {
            float p0=p[i*4+0], p1=p[i*4+1], p2=p[i*4+2], p3=p[i*4+3];
            float r0 = p0*w0[0] + p1*w0[4] + p2*w0[8]  + p3*w0[12];
            float r1 = p0*w0[1] + p1*w0[5] + p2*w0[9]  + p3*w0[13];
            float r2 = p0*w0[2] + p1*w0[6] + p2*w0[10] + p3*w0[14];
            float r3 = p0*w0[3] + p1*w0[7] + p2*w0[11] + p3*w0[15];
            hh[2*i+0] = __floats2half2_rn(r0, r1);
            hh[2*i+1] = __floats2half2_rn(r2, r3);
        }
        uint4* dst = (uint4*)(vbase + (size_t)pair*16);
        uint4 u0, u1;
        u0.x = *(unsigned*)&hh[0]; u0.y = *(unsigned*)&hh[1];
        u0.z = *(unsigned*)&hh[2]; u0.w = *(unsigned*)&hh[3];
        u1.x = *(unsigned*)&hh[4]; u1.y = *(unsigned*)&hh[5];
        u1.z = *(unsigned*)&hh[6]; u1.w = *(unsigned*)&hh[7];
        dst[0] = u0; dst[1] = u1;
    }
    __syncthreads();

    // ---- Iter 0 m-step (r_hat = ck/32 analytically) + stats0 + zero buffers ----
    {
        const int khalf = tid >> 8;
        const int idx   = tid & 255;
        const int o     = idx >> 3;
        const int sp    = idx & 7;
        const __half2* vp2 = (const __half2*)vbase + idx;
        float m0 = 0.f, m1 = 0.f, q0 = 0.f, q1 = 0.f;
        const int k0 = khalf * KH;
        #pragma unroll 4
        for (int k = k0; k < k0 + KH; ++k) {
            float2 v = __half22float2(vp2[(size_t)k*256]);
            float r  = sCk[k] * 0.03125f;
            m0 += r*v.x; m1 += r*v.y;
            q0 += r*v.x*v.x; q1 += r*v.y*v.y;
        }
        if (khalf) {
            float* pp = sPart + idx*4;
            pp[0]=m0; pp[1]=m1; pp[2]=q0; pp[3]=q1;
        }
        __syncthreads();
        if (khalf) {
            // idle half zeroes accumulators for the first fused pass
            for (int z = idx; z < 512; z += 256) { sM[z] = 0.f; sQ[z] = 0.f; }
            if (idx < 32) sRsA[idx] = 0.f;
        } else {
            const float* pp = sPart + idx*4;
            float rs  = (*sCkS) * 0.03125f;      // rsum0 (same for every o)
            float irs = 1.f/(rs + CEPS);
            float s1  = rs/(rs + CEPS);
            m0 = (m0 + pp[0]) * irs;
            m1 = (m1 + pp[1]) * irs;
            q0 = (q0 + pp[2]) * irs;
            q1 = (q1 + pp[3]) * irs;
            float v0 = fmaxf(q0 - m0*m0*(2.f - s1), 0.f) + CEPS;
            float v1 = fmaxf(q1 - m1*m1*(2.f - s1), 0.f) + CEPS;
            sMean[o*17 + 2*sp]     = m0;
            sMean[o*17 + 2*sp + 1] = m1;
            sIv[o*17 + 2*sp]       = 0.5f/v0;
            sIv[o*17 + 2*sp + 1]   = 0.5f/v1;
            float sl = 0.5f*(__logf(v0) + __logf(v1));
            #pragma unroll
            for (int off = 1; off < 8; off <<= 1)
                sl += __shfl_xor_sync(0xffffffffu, sl, off);
            if (sp == 0) {
                float cost = (16.f*beta_u[o] + sl) * rs;
                float z = 0.0011f * (beta_a[o] - cost);
                float a = 1.f/(1.f + __expf(-z));
                sAct[o] = a;
                sC[o]   = __logf(a) - sl - 8.f*LN2PI;
            }
        }
    }
    __syncthreads();

    // ---- Two fused (e-step + m-accumulate) passes + stats phases ----
    #pragma unroll 1
    for (int it = 0; it < 2; ++it) {
        float* rsCur = it ? sRsB : sRsA;
        float* rsNxt = it ? sRsA : sRsB;   // zeroed for it==0 only when it==0's stats runs
        const float lam = it ? 0.0013f : 0.0012f;

        // fused pass: e-step from current stats, accumulate M/Q/rsum
        {
            const int o  = tid & 31;
            const int wk = tid >> 5;
            __half2 mh[8], ivh[8];
            #pragma unroll
            for (int h = 0; h < 8; ++h) {
                mh[h]  = __floats2half2_rn(sMean[o*17 + 2*h], sMean[o*17 + 2*h+1]);
                ivh[h] = __floats2half2_rn(sIv[o*17 + 2*h],   sIv[o*17 + 2*h+1]);
            }
            const float Co = sC[o];
            float macc[16], qacc[16];
            #pragma unroll
            for (int s = 0; s < 16; ++s) { macc[s] = 0.f; qacc[s] = 0.f; }
            float racc = 0.f;
            const uint4* vr = (const uint4*)vbase;
            for (int i = 0; i < 18; ++i) {
                int k = wk + (i << 4);
                size_t ro = (size_t)(k*32 + o)*2;
                uint4 u0 = vr[ro];
                uint4 u1 = vr[ro + 1];
                float acc = 0.f;
                #pragma unroll
                for (int h = 0; h < 8; ++h) {
                    unsigned u = (h < 4) ? (&u0.x)[h] : (&u1.x)[h-4];
                    float2 f  = __half22float2(*(__half2*)&u);
                    float2 mm = __half22float2(mh[h]);
                    float2 iv = __half22float2(ivh[h]);
                    float d0 = f.x - mm.x;
                    float d1 = f.y - mm.y;
                    acc += d0*d0*iv.x + d1*d1*iv.y;
                }
                float lnap = Co - acc;
                float mx = lnap;
                #pragma unroll
                for (int off = 16; off; off >>= 1)
                    mx = fmaxf(mx, __shfl_xor_sync(0xffffffffu, mx, off));
                float e  = __expf(lnap - mx);
                float se = e;
                #pragma unroll
                for (int off = 16; off; off >>= 1)
                    se += __shfl_xor_sync(0xffffffffu, se, off);
                float rh = (e/se) * sCk[k];   // exact r*a, o-normalized
                racc += rh;
                #pragma unroll
                for (int h = 0; h < 8; ++h) {
                    unsigned u = (h < 4) ? (&u0.x)[h] : (&u1.x)[h-4];
                    float2 f = __half22float2(*(__half2*)&u);
                    macc[2*h]   += rh*f.x;
                    macc[2*h+1] += rh*f.y;
                    qacc[2*h]   += rh*f.x*f.x;
                    qacc[2*h+1] += rh*f.y*f.y;
                }
            }
            #pragma unroll
            for (int s = 0; s < 16; ++s) {
                atomicAdd(&sM[o*16 + s], macc[s]);
                atomicAdd(&sQ[o*16 + s], qacc[s]);
            }
            atomicAdd(&rsCur[o], racc);
        }
        __syncthreads();

        // stats phase: finalize mean/var/act/C; zero buffers for next pass
        {
            const int o = tid >> 4;
            const int s = tid & 15;
            float rs  = rsCur[o];
            float irs = 1.f/(rs + CEPS);
            float s1  = rs/(rs + CEPS);
            float M = sM[o*16 + s] * irs;
            float Q = sQ[o*16 + s] * irs;
            float var = fmaxf(Q - M*M*(2.f - s1), 0.f) + CEPS;
            sMean[o*17 + s] = M;
            sIv[o*17 + s]   = 0.5f/var;
            float sl = 0.5f*__logf(var);
            #pragma unroll
            for (int off = 8; off; off >>= 1)
                sl += __shfl_xor_sync(0xffffffffu, sl, off);
            if (s == 0) {
                float cost = (16.f*beta_u[o] + sl) * rs;
                float z = lam * (beta_a[o] - cost);
                float a = 1.f/(1.f + __expf(-z));
                sAct[o] = a;
                sC[o]   = __logf(a) - sl - 8.f*LN2PI;
            }
            sM[o*16 + s] = 0.f;
            sQ[o*16 + s] = 0.f;
            if (tid < 32) rsNxt[tid] = 0.f;
        }
        __syncthreads();
    }

    // ---- output: [n, 544] = concat(mean[32*16], act[32]) ----
    {
        int o = tid >> 4, s = tid & 15;
        out[(size_t)n*544 + tid] = sMean[o*17 + s];
        if (tid < 32)
            out[(size_t)n*544 + 512 + tid] = sAct[tid];
    }
}

extern "C" void kernel_launch(void* const* d_in, const int* in_sizes, int n_in,
                              void* d_out, int out_size)
{
    const float* x  = (const float*)d_in[0];
    const float* w  = (const float*)d_in[1];
    const float* bu = (const float*)d_in[2];
    const float* ba = (const float*)d_in[3];
    float* out = (float*)d_out;

    const int smem_bytes = 7200 * 4;   // ~28.8 KB; occupancy capped by regs at 2 CTAs/SM
    cudaFuncSetAttribute(convcaps_kernel,
                         cudaFuncAttributeMaxDynamicSharedMemorySize, smem_bytes);
    convcaps_kernel<<<NPOS, NTHREADS, smem_bytes>>>(x, w, bu, ba, out);
}